// round 13
// baseline (speedup 1.0000x reference)
#include <cuda_runtime.h>
#include <cstdint>

#define BATCH 8
#define SEQ   1024
#define EMB   1024
#define NHEAD 16
#define HDIM  64

// ---------------- scratch (static device globals: allocation-free) ----------
__device__ float g_Q[BATCH * SEQ * EMB];
__device__ float g_K[BATCH * SEQ * EMB];
__device__ float g_V[BATCH * SEQ * EMB];
__device__ float g_A[BATCH * SEQ * EMB];
__device__ float g_X[BATCH * SEQ * EMB];

// ---------------- helpers -----------------------------------------------------
__device__ __forceinline__ float to_tf32(float x) {
    uint32_t u;
    asm("cvt.rna.tf32.f32 %0, %1;" : "=r"(u) : "f"(x));
    return __uint_as_float(u);
}

__device__ __forceinline__ uint32_t smem_u32(const void* p) {
    return (uint32_t)__cvta_generic_to_shared(p);
}

// D += A(16x8,row) * B(8x8,col)  tf32, fp32 accum.
// PTX m16n8k8 tf32 fragments (g = lane>>2, t = lane&3):
//   A: a0=A[g][t], a1=A[g+8][t], a2=A[g][t+4], a3=A[g+8][t+4]
//   B: b0=B[t][g], b1=B[t+4][g]
//   C: c0=C[g][2t], c1=C[g][2t+1], c2=C[g+8][2t], c3=C[g+8][2t+1]
#define MMA_TF32(acc, a0, a1, a2, a3, b0, b1)                                  \
    asm volatile(                                                              \
        "mma.sync.aligned.m16n8k8.row.col.f32.tf32.tf32.f32 "                  \
        "{%0,%1,%2,%3}, {%4,%5,%6,%7}, {%8,%9}, {%0,%1,%2,%3};"                \
        : "+f"((acc)[0]), "+f"((acc)[1]), "+f"((acc)[2]), "+f"((acc)[3])       \
        : "r"(a0), "r"(a1), "r"(a2), "r"(a3), "r"(b0), "r"(b1))

// ldmatrix x4 on b32 data: each m8n8.b16 matrix = 8 rows x 16 bytes = 8x4 floats.
#define LDSM_X4(r0, r1, r2, r3, addr)                                          \
    asm volatile(                                                              \
        "ldmatrix.sync.aligned.m8n8.x4.shared.b16 {%0,%1,%2,%3}, [%4];"        \
        : "=r"(r0), "=r"(r1), "=r"(r2), "=r"(r3) : "r"(addr))

// =====================  mma.sync tf32 multiway GEMM  =========================
// 128x256 CTA tile, 8 warps (wm in {0,1} x wn in {0..3}), warp tile 64x64.
// Rows of the 16-float k-chunk are stored with XOR swizzle
//   physical_chunk = logical_chunk ^ ((row>>1) & 3)
// which is conflict-free for both STS.128 staging and all ldmatrix phases.
#define GKC  16
#define NCHK (EMB / GKC)
#define TM   128
#define TN   256
// dynamic smem floats: aS 2*128*16, bS 2*256*16, rowIdx 128 ints
#define ASTRIDE 2048
#define BSTRIDE 4096
#define GEMM_SMEM ((2 * ASTRIDE + 2 * BSTRIDE + 128) * 4)

__global__ __launch_bounds__(256, 1) void mw_gemm_mma(
    const float* __restrict__ X,
    const float* __restrict__ Wt, const float* __restrict__ bt,
    const float* __restrict__ Wi, const float* __restrict__ bi,
    float* __restrict__ Y,
    const int* __restrict__ split_ptr, float alpha)
{
    extern __shared__ float gsm[];
    float* aS = gsm;                       // [2][128][16]
    float* bS = gsm + 2 * ASTRIDE;         // [2][256][16]
    int* rowIdx = (int*)(gsm + 2 * ASTRIDE + 2 * BSTRIDE);

    const int tid  = threadIdx.x;
    const int lane = tid & 31;
    const int wid  = tid >> 5;
    const int wm   = wid & 1;          // 64-row half
    const int wn   = wid >> 1;         // 64-col quarter
    const int g    = lane >> 2;
    const int t    = lane & 3;
    const int l7   = lane & 7;
    const int lb8  = (lane >> 3) & 1;
    const int lh4  = lane >> 4;

    const int n0    = blockIdx.x * TN;
    const int mtile = blockIdx.y;

    int split = *split_ptr;
    if (split < 0) split = 0;
    if (split > SEQ) split = SEQ;
    const int textRows = BATCH * split;

    if (tid < 128) {
        int idx = mtile * TM + tid;
        int r;
        if (idx < textRows) {
            int b = (split > 0) ? (idx / split) : 0;
            int tt = (split > 0) ? (idx - b * split) : 0;
            r = b * SEQ + tt;
        } else {
            int per = SEQ - split;
            int j = idx - textRows;
            int b = (per > 0) ? (j / per) : 0;
            int tt = split + ((per > 0) ? (j - b * per) : 0);
            r = b * SEQ + tt;
        }
        rowIdx[tid] = r;
    }
    const bool isText = (mtile * TM) < textRows;
    const float* __restrict__ W    = isText ? Wt : Wi;
    const float* __restrict__ bias = isText ? bt : bi;
    __syncthreads();

    // staging coords (A: 2 chunks/thread, B: 4 chunks/thread)
    const int cA = tid & 3;
    int rA[2], stA[2];           // float offsets into a buffer
#pragma unroll
    for (int i = 0; i < 2; i++) {
        rA[i] = (tid + i * 256) >> 2;
        stA[i] = rA[i] * 16 + ((cA ^ ((rA[i] >> 1) & 3)) * 4);
    }
    int rB[4], stB[4];
#pragma unroll
    for (int i = 0; i < 4; i++) {
        rB[i] = (tid + i * 256) >> 2;
        stB[i] = rB[i] * 16 + ((cA ^ ((rB[i] >> 1) & 3)) * 4);
    }

    // ldmatrix lane bases (byte offsets computed per use)
    const int rowA = wm * 64 + l7 + lb8 * 8;          // + mt*16
    const int xa   = ((l7 + 8 * lb8) >> 1) & 3;
    const int rowB = wn * 64 + lh4 * 8 + l7;          // + ntp*16
    const int xb   = ((lh4 * 8 + l7) >> 1) & 3;
    const uint32_t aBase = smem_u32(aS) + (uint32_t)(rowA * 16 * 4);
    const uint32_t bBase = smem_u32(bS) + (uint32_t)(rowB * 16 * 4);
    // per-(ks,half) swizzled chunk byte offsets
    uint32_t caOff[2], cbOff[2];
#pragma unroll
    for (int ks = 0; ks < 2; ks++) {
        caOff[ks] = (uint32_t)((((2 * ks + lh4) ^ xa) * 4) * 4);
        cbOff[ks] = (uint32_t)((((2 * ks + lb8) ^ xb) * 4) * 4);
    }

    float acc[4][8][4];
#pragma unroll
    for (int mt = 0; mt < 4; mt++)
#pragma unroll
        for (int nt = 0; nt < 8; nt++)
#pragma unroll
            for (int c = 0; c < 4; c++) acc[mt][nt][c] = 0.f;

    // ---- stage chunk 0 into buffer 0 ----
#pragma unroll
    for (int i = 0; i < 2; i++) {
        float4 v = *(const float4*)(X + (size_t)rowIdx[rA[i]] * EMB + cA * 4);
        v.x = to_tf32(v.x); v.y = to_tf32(v.y);
        v.z = to_tf32(v.z); v.w = to_tf32(v.w);
        *(float4*)(aS + stA[i]) = v;
    }
#pragma unroll
    for (int i = 0; i < 4; i++) {
        float4 v = *(const float4*)(W + (size_t)(n0 + rB[i]) * EMB + cA * 4);
        v.x = to_tf32(v.x); v.y = to_tf32(v.y);
        v.z = to_tf32(v.z); v.w = to_tf32(v.w);
        *(float4*)(bS + stB[i]) = v;
    }
    __syncthreads();

    for (int ic = 0; ic < NCHK; ic++) {
        const int p = ic & 1;
        const uint32_t aBuf = aBase + (uint32_t)(p * ASTRIDE * 4);
        const uint32_t bBuf = bBase + (uint32_t)(p * BSTRIDE * 4);
        float4 pa[2], pb[4];
        const bool more = (ic + 1) < NCHK;
        if (more) {
            const int k0 = (ic + 1) * GKC;
#pragma unroll
            for (int i = 0; i < 2; i++)
                pa[i] = *(const float4*)(X + (size_t)rowIdx[rA[i]] * EMB + k0 + cA * 4);
#pragma unroll
            for (int i = 0; i < 4; i++)
                pb[i] = *(const float4*)(W + (size_t)(n0 + rB[i]) * EMB + k0 + cA * 4);
        }

#pragma unroll
        for (int ks = 0; ks < 2; ks++) {
            uint32_t afr[4][4];
#pragma unroll
            for (int mt = 0; mt < 4; mt++)
                LDSM_X4(afr[mt][0], afr[mt][1], afr[mt][2], afr[mt][3],
                        aBuf + (uint32_t)(mt * 16 * 16 * 4) + caOff[ks]);
            uint32_t bfr[8][2];
#pragma unroll
            for (int ntp = 0; ntp < 4; ntp++)
                LDSM_X4(bfr[2 * ntp][0], bfr[2 * ntp][1],
                        bfr[2 * ntp + 1][0], bfr[2 * ntp + 1][1],
                        bBuf + (uint32_t)(ntp * 16 * 16 * 4) + cbOff[ks]);
#pragma unroll
            for (int mt = 0; mt < 4; mt++)
#pragma unroll
                for (int nt = 0; nt < 8; nt++)
                    MMA_TF32(acc[mt][nt],
                             afr[mt][0], afr[mt][1], afr[mt][2], afr[mt][3],
                             bfr[nt][0], bfr[nt][1]);
        }

        if (more) {
            float* aN = aS + (p ^ 1) * ASTRIDE;
            float* bN = bS + (p ^ 1) * BSTRIDE;
#pragma unroll
            for (int i = 0; i < 2; i++) {
                float4 v = pa[i];
                v.x = to_tf32(v.x); v.y = to_tf32(v.y);
                v.z = to_tf32(v.z); v.w = to_tf32(v.w);
                *(float4*)(aN + stA[i]) = v;
            }
#pragma unroll
            for (int i = 0; i < 4; i++) {
                float4 v = pb[i];
                v.x = to_tf32(v.x); v.y = to_tf32(v.y);
                v.z = to_tf32(v.z); v.w = to_tf32(v.w);
                *(float4*)(bN + stB[i]) = v;
            }
        }
        __syncthreads();
    }

    // ---- epilogue: bias + alpha, float2 stores ----
#pragma unroll
    for (int mt = 0; mt < 4; mt++) {
        const int r0 = rowIdx[wm * 64 + mt * 16 + g];
        const int r1 = rowIdx[wm * 64 + mt * 16 + g + 8];
#pragma unroll
        for (int nt = 0; nt < 8; nt++) {
            const int nc = n0 + wn * 64 + nt * 8 + t * 2;
            float2 bb = *(const float2*)(bias + nc);
            float2 o;
            o.x = (acc[mt][nt][0] + bb.x) * alpha;
            o.y = (acc[mt][nt][1] + bb.y) * alpha;
            *(float2*)(Y + (size_t)r0 * EMB + nc) = o;
            o.x = (acc[mt][nt][2] + bb.x) * alpha;
            o.y = (acc[mt][nt][3] + bb.y) * alpha;
            *(float2*)(Y + (size_t)r1 * EMB + nc) = o;
        }
    }
}

// =====================  mma.sync tf32 flash attention  =======================
// (unchanged from R12: qS persistent in smem, occ 2)
#define ATP 68

__global__ __launch_bounds__(256, 2) void attn_mma(
    const float* __restrict__ Q, const float* __restrict__ K,
    const float* __restrict__ V, const float* __restrict__ mask,
    float* __restrict__ O)
{
    extern __shared__ float dynsm[];
    float (*qS)[ATP] = (float(*)[ATP])(dynsm);              // 128 x 68 (Q, persistent)
    float (*pS)[ATP] = (float(*)[ATP])(dynsm + 128 * ATP);  // 128 x 68 (P)
    float (*kS)[ATP] = (float(*)[ATP])(dynsm + 256 * ATP);  // 64 x 68
    float (*vS)[ATP] = (float(*)[ATP])(dynsm + 320 * ATP);  // 64 x 68
    float (*lred)[2] = (float(*)[2])(dynsm + 384 * ATP);    // 128 x 2

    const int tid  = threadIdx.x;
    const int lane = tid & 31;
    const int wid  = tid >> 5;
    const int wm   = wid >> 1;
    const int wn   = wid & 1;
    const int g    = lane >> 2;
    const int t    = lane & 3;
    const int l7   = lane & 7;
    const int lb8  = (lane >> 3) & 1;
    const int lh4  = lane >> 4;

    const int t0 = blockIdx.x * 128;
    const int h  = blockIdx.y;
    const int b  = blockIdx.z;

    const float* Qb = Q + ((size_t)b * SEQ + t0) * EMB + h * HDIM;
    const float* Kb = K + (size_t)b * SEQ * EMB + h * HDIM;
    const float* Vb = V + (size_t)b * SEQ * EMB + h * HDIM;

    const uint32_t qAaddr = smem_u32(&qS[wm * 32 + l7 + lb8 * 8][lh4 * 4]);
    const uint32_t pAaddr = smem_u32(&pS[wm * 32 + l7 + lb8 * 8][lh4 * 4]);
    const uint32_t kBaddr = smem_u32(&kS[wn * 32 + lh4 * 8 + l7][lb8 * 4]);

#pragma unroll
    for (int i = 0; i < 8; i++) {
        int id = tid + i * 256;
        int r = id >> 4, d4 = id & 15;
        float4 v = *(const float4*)(Qb + (size_t)r * EMB + d4 * 4);
        v.x = to_tf32(v.x); v.y = to_tf32(v.y);
        v.z = to_tf32(v.z); v.w = to_tf32(v.w);
        *(float4*)&qS[r][d4 * 4] = v;
    }

#pragma unroll
    for (int i = 0; i < 4; i++) {
        int id = tid + i * 256;
        int s = id >> 4, d4 = id & 15;
        float4 kv = *(const float4*)(Kb + (size_t)s * EMB + d4 * 4);
        float4 vv = *(const float4*)(Vb + (size_t)s * EMB + d4 * 4);
        kv.x = to_tf32(kv.x); kv.y = to_tf32(kv.y);
        kv.z = to_tf32(kv.z); kv.w = to_tf32(kv.w);
        vv.x = to_tf32(vv.x); vv.y = to_tf32(vv.y);
        vv.z = to_tf32(vv.z); vv.w = to_tf32(vv.w);
        *(float4*)&kS[s][d4 * 4] = kv;
        *(float4*)&vS[s][d4 * 4] = vv;
    }
    __syncthreads();

    float oa[2][4][4];
#pragma unroll
    for (int mt = 0; mt < 2; mt++)
#pragma unroll
        for (int nt = 0; nt < 4; nt++)
#pragma unroll
            for (int c = 0; c < 4; c++) oa[mt][nt][c] = 0.f;
    float lp[2][2] = {{0.f, 0.f}, {0.f, 0.f}};

    for (int ic = 0; ic < SEQ / 64; ic++) {
        const int s0 = ic * 64;
        const bool more = (ic + 1) < SEQ / 64;
        float4 pk[4], pv[4];
        if (more) {
            const int sn = s0 + 64;
#pragma unroll
            for (int i = 0; i < 4; i++) {
                int id = tid + i * 256;
                int s = id >> 4, d4 = id & 15;
                pk[i] = *(const float4*)(Kb + (size_t)(sn + s) * EMB + d4 * 4);
                pv[i] = *(const float4*)(Vb + (size_t)(sn + s) * EMB + d4 * 4);
            }
        }

        float sa[2][4][4];
#pragma unroll
        for (int mt = 0; mt < 2; mt++)
#pragma unroll
            for (int nt = 0; nt < 4; nt++)
#pragma unroll
                for (int c = 0; c < 4; c++) sa[mt][nt][c] = 0.f;
#pragma unroll
        for (int ks = 0; ks < 8; ks++) {
            uint32_t qf[2][4];
#pragma unroll
            for (int mt = 0; mt < 2; mt++)
                LDSM_X4(qf[mt][0], qf[mt][1], qf[mt][2], qf[mt][3],
                        qAaddr + (uint32_t)((mt * 16 * ATP + ks * 8) * 4));
            uint32_t bk[4][2];
#pragma unroll
            for (int ntp = 0; ntp < 2; ntp++)
                LDSM_X4(bk[2 * ntp][0], bk[2 * ntp][1],
                        bk[2 * ntp + 1][0], bk[2 * ntp + 1][1],
                        kBaddr + (uint32_t)((ntp * 16 * ATP + ks * 8) * 4));
#pragma unroll
            for (int mt = 0; mt < 2; mt++)
#pragma unroll
                for (int nt = 0; nt < 4; nt++)
                    MMA_TF32(sa[mt][nt],
                             qf[mt][0], qf[mt][1], qf[mt][2], qf[mt][3],
                             bk[nt][0], bk[nt][1]);
        }

#pragma unroll
        for (int mt = 0; mt < 2; mt++) {
            const int lr0 = wm * 32 + mt * 16 + g;
            const size_t gr0 = (size_t)(t0 + lr0) * SEQ + s0;
            const size_t gr1 = gr0 + (size_t)8 * SEQ;
#pragma unroll
            for (int nt = 0; nt < 4; nt++) {
                const int c = wn * 32 + nt * 8 + 2 * t;
                float2 m0 = *(const float2*)(mask + gr0 + c);
                float2 m1 = *(const float2*)(mask + gr1 + c);
                float p00 = __expf(sa[mt][nt][0] + m0.x);
                float p01 = __expf(sa[mt][nt][1] + m0.y);
                float p10 = __expf(sa[mt][nt][2] + m1.x);
                float p11 = __expf(sa[mt][nt][3] + m1.y);
                lp[mt][0] += p00 + p01;
                lp[mt][1] += p10 + p11;
                float2 st;
                st.x = to_tf32(p00); st.y = to_tf32(p01);
                *(float2*)&pS[lr0][c] = st;
                st.x = to_tf32(p10); st.y = to_tf32(p11);
                *(float2*)&pS[lr0 + 8][c] = st;
            }
        }
        __syncthreads();

#pragma unroll
        for (int ks = 0; ks < 8; ks++) {
            const int kc = ks * 8 + t;
            uint32_t af[2][4];
#pragma unroll
            for (int mt = 0; mt < 2; mt++)
                LDSM_X4(af[mt][0], af[mt][1], af[mt][2], af[mt][3],
                        pAaddr + (uint32_t)((mt * 16 * ATP + ks * 8) * 4));
            uint32_t bv[4][2];
#pragma unroll
            for (int nt = 0; nt < 4; nt++) {
                const int cn = wn * 32 + nt * 8 + g;
                bv[nt][0] = __float_as_uint(vS[kc][cn]);
                bv[nt][1] = __float_as_uint(vS[kc + 4][cn]);
            }
#pragma unroll
            for (int mt = 0; mt < 2; mt++)
#pragma unroll
                for (int nt = 0; nt < 4; nt++)
                    MMA_TF32(oa[mt][nt],
                             af[mt][0], af[mt][1], af[mt][2], af[mt][3],
                             bv[nt][0], bv[nt][1]);
        }
        __syncthreads();

        if (more) {
#pragma unroll
            for (int i = 0; i < 4; i++) {
                int id = tid + i * 256;
                int s = id >> 4, d4 = id & 15;
                float4 kv = pk[i], vv = pv[i];
                kv.x = to_tf32(kv.x); kv.y = to_tf32(kv.y);
                kv.z = to_tf32(kv.z); kv.w = to_tf32(kv.w);
                vv.x = to_tf32(vv.x); vv.y = to_tf32(vv.y);
                vv.z = to_tf32(vv.z); vv.w = to_tf32(vv.w);
                *(float4*)&kS[s][d4 * 4] = kv;
                *(float4*)&vS[s][d4 * 4] = vv;
            }
            __syncthreads();
        }
    }

#pragma unroll
    for (int mt = 0; mt < 2; mt++) {
#pragma unroll
        for (int j = 0; j < 2; j++) {
            lp[mt][j] += __shfl_xor_sync(0xffffffffu, lp[mt][j], 1);
            lp[mt][j] += __shfl_xor_sync(0xffffffffu, lp[mt][j], 2);
        }
    }
    if (t == 0) {
#pragma unroll
        for (int mt = 0; mt < 2; mt++) {
            lred[wm * 32 + mt * 16 + g][wn]     = lp[mt][0];
            lred[wm * 32 + mt * 16 + g + 8][wn] = lp[mt][1];
        }
    }
    __syncthreads();

    float* Ob = O + ((size_t)b * SEQ + t0) * EMB + h * HDIM;
#pragma unroll
    for (int mt = 0; mt < 2; mt++) {
        const int lr0 = wm * 32 + mt * 16 + g;
        const float inv0 = 1.f / (lred[lr0][0] + lred[lr0][1]);
        const float inv1 = 1.f / (lred[lr0 + 8][0] + lred[lr0 + 8][1]);
#pragma unroll
        for (int nt = 0; nt < 4; nt++) {
            const int c = wn * 32 + nt * 8 + 2 * t;
            float2 o;
            o.x = oa[mt][nt][0] * inv0;
            o.y = oa[mt][nt][1] * inv0;
            *(float2*)(Ob + (size_t)lr0 * EMB + c) = o;
            o.x = oa[mt][nt][2] * inv1;
            o.y = oa[mt][nt][3] * inv1;
            *(float2*)(Ob + (size_t)(lr0 + 8) * EMB + c) = o;
        }
    }
}

#define ATTN_SMEM ((384 * ATP + 256) * 4)

// ---------------- multiway layernorm over last dim (E=1024) -----------------
__global__ __launch_bounds__(256) void ln_kernel(
    const float* __restrict__ A, float* __restrict__ Xo,
    const float* __restrict__ gt, const float* __restrict__ bt,
    const float* __restrict__ gi, const float* __restrict__ bi,
    const int* __restrict__ split_ptr)
{
    const int r = blockIdx.x;
    const int t = r & (SEQ - 1);
    const int split = *split_ptr;
    const float* g  = (t < split) ? gt : gi;
    const float* bb = (t < split) ? bt : bi;

    const int tid = threadIdx.x;
    float4 v = ((const float4*)(A + (size_t)r * EMB))[tid];

    float s  = v.x + v.y + v.z + v.w;
    float sq = v.x * v.x + v.y * v.y + v.z * v.z + v.w * v.w;

    __shared__ float ssum[8], ssq[8];
#pragma unroll
    for (int off = 16; off > 0; off >>= 1) {
        s  += __shfl_down_sync(0xffffffffu, s, off);
        sq += __shfl_down_sync(0xffffffffu, sq, off);
    }
    if ((tid & 31) == 0) { ssum[tid >> 5] = s; ssq[tid >> 5] = sq; }
    __syncthreads();

    __shared__ float mu_s, rs_s;
    if (tid == 0) {
        float S = 0.f, Qq = 0.f;
#pragma unroll
        for (int i = 0; i < 8; i++) { S += ssum[i]; Qq += ssq[i]; }
        float mu  = S * (1.f / EMB);
        float var = Qq * (1.f / EMB) - mu * mu;
        mu_s = mu;
        rs_s = rsqrtf(var + 1e-5f);
    }
    __syncthreads();
    float mu = mu_s, rstd = rs_s;

    float4 g4 = ((const float4*)g)[tid];
    float4 b4 = ((const float4*)bb)[tid];
    float4 y;
    y.x = (v.x - mu) * rstd * g4.x + b4.x;
    y.y = (v.y - mu) * rstd * g4.y + b4.y;
    y.z = (v.z - mu) * rstd * g4.z + b4.z;
    y.w = (v.w - mu) * rstd * g4.w + b4.w;
    ((float4*)(Xo + (size_t)r * EMB))[tid] = y;
}

// ---------------- launch ------------------------------------------------------
extern "C" void kernel_launch(void* const* d_in, const int* in_sizes, int n_in,
                              void* d_out, int out_size)
{
    const float* query = (const float*)d_in[0];
    const float* key   = (const float*)d_in[1];
    const float* value = (const float*)d_in[2];
    const float* mask  = (const float*)d_in[3];
    const float* Wq_t = (const float*)d_in[4];  const float* bq_t = (const float*)d_in[5];
    const float* Wq_i = (const float*)d_in[6];  const float* bq_i = (const float*)d_in[7];
    const float* Wk_t = (const float*)d_in[8];  const float* bk_t = (const float*)d_in[9];
    const float* Wk_i = (const float*)d_in[10]; const float* bk_i = (const float*)d_in[11];
    const float* Wv_t = (const float*)d_in[12]; const float* bv_t = (const float*)d_in[13];
    const float* Wv_i = (const float*)d_in[14]; const float* bv_i = (const float*)d_in[15];
    const float* Wo_t = (const float*)d_in[16]; const float* bo_t = (const float*)d_in[17];
    const float* Wo_i = (const float*)d_in[18]; const float* bo_i = (const float*)d_in[19];
    const float* lng_t = (const float*)d_in[20]; const float* lnb_t = (const float*)d_in[21];
    const float* lng_i = (const float*)d_in[22]; const float* lnb_i = (const float*)d_in[23];
    const int*   split = (const int*)d_in[24];

    float *Q, *K, *V, *A, *X;
    cudaGetSymbolAddress((void**)&Q, g_Q);
    cudaGetSymbolAddress((void**)&K, g_K);
    cudaGetSymbolAddress((void**)&V, g_V);
    cudaGetSymbolAddress((void**)&A, g_A);
    cudaGetSymbolAddress((void**)&X, g_X);

    const float scaling = 0.125f; // HD^-0.5, HD=64

    static bool attr_done = false;
    if (!attr_done) {
        cudaFuncSetAttribute(attn_mma, cudaFuncAttributeMaxDynamicSharedMemorySize,
                             ATTN_SMEM);
        cudaFuncSetAttribute(mw_gemm_mma, cudaFuncAttributeMaxDynamicSharedMemorySize,
                             GEMM_SMEM);
        attr_done = true;
    }

    dim3 gg(EMB / TN, (BATCH * SEQ) / TM);
    mw_gemm_mma<<<gg, 256, GEMM_SMEM>>>(query, Wq_t, bq_t, Wq_i, bq_i, Q, split, scaling);
    mw_gemm_mma<<<gg, 256, GEMM_SMEM>>>(key,   Wk_t, bk_t, Wk_i, bk_i, K, split, 1.f);
    mw_gemm_mma<<<gg, 256, GEMM_SMEM>>>(value, Wv_t, bv_t, Wv_i, bv_i, V, split, 1.f);

    dim3 ga(SEQ / 128, NHEAD, BATCH);
    attn_mma<<<ga, 256, ATTN_SMEM>>>(Q, K, V, mask, A);

    ln_kernel<<<BATCH * SEQ, 256>>>(A, X, lng_t, lnb_t, lng_i, lnb_i, split);

    mw_gemm_mma<<<gg, 256, GEMM_SMEM>>>(X, Wo_t, bo_t, Wo_i, bo_i, (float*)d_out, split, 1.f);
}

// round 14
// speedup vs baseline: 1.1069x; 1.1069x over previous
#include <cuda_runtime.h>
#include <cstdint>

#define BATCH 8
#define SEQ   1024
#define EMB   1024
#define NHEAD 16
#define HDIM  64

// ---------------- scratch (static device globals: allocation-free) ----------
__device__ float g_Q[BATCH * SEQ * EMB];
__device__ float g_K[BATCH * SEQ * EMB];
__device__ float g_V[BATCH * SEQ * EMB];
__device__ float g_A[BATCH * SEQ * EMB];
__device__ float g_X[BATCH * SEQ * EMB];

// ---------------- helpers -----------------------------------------------------
__device__ __forceinline__ float to_tf32(float x) {
    uint32_t u;
    asm("cvt.rna.tf32.f32 %0, %1;" : "=r"(u) : "f"(x));
    return __uint_as_float(u);
}

__device__ __forceinline__ uint32_t smem_u32(const void* p) {
    return (uint32_t)__cvta_generic_to_shared(p);
}

// D += A(16x8,row) * B(8x8,col)  tf32, fp32 accum.
// PTX m16n8k8 tf32 fragments (g = lane>>2, t = lane&3):
//   A: a0=A[g][t], a1=A[g+8][t], a2=A[g][t+4], a3=A[g+8][t+4]
//   B: b0=B[t][g], b1=B[t+4][g]
//   C: c0=C[g][2t], c1=C[g][2t+1], c2=C[g+8][2t], c3=C[g+8][2t+1]
#define MMA_TF32(acc, a0, a1, a2, a3, b0, b1)                                  \
    asm volatile(                                                              \
        "mma.sync.aligned.m16n8k8.row.col.f32.tf32.tf32.f32 "                  \
        "{%0,%1,%2,%3}, {%4,%5,%6,%7}, {%8,%9}, {%0,%1,%2,%3};"                \
        : "+f"((acc)[0]), "+f"((acc)[1]), "+f"((acc)[2]), "+f"((acc)[3])       \
        : "r"(a0), "r"(a1), "r"(a2), "r"(a3), "r"(b0), "r"(b1))

// ldmatrix x4 on b32 data: each m8n8.b16 matrix = 8 rows x 16 bytes = 8x4 floats.
#define LDSM_X4(r0, r1, r2, r3, addr)                                          \
    asm volatile(                                                              \
        "ldmatrix.sync.aligned.m8n8.x4.shared.b16 {%0,%1,%2,%3}, [%4];"        \
        : "=r"(r0), "=r"(r1), "=r"(r2), "=r"(r3) : "r"(addr))

// =====================  mma.sync tf32 multiway GEMM  =========================
// 128x128 CTA tile, occ 2 (R12 config — best measured GEMM).
#define GKC  16
#define NCHK (EMB / GKC)
#define PAD  20

__global__ __launch_bounds__(256, 2) void mw_gemm_mma(
    const float* __restrict__ X,
    const float* __restrict__ Wt, const float* __restrict__ bt,
    const float* __restrict__ Wi, const float* __restrict__ bi,
    float* __restrict__ Y,
    const int* __restrict__ split_ptr, float alpha)
{
    __shared__ float aS[2][128][PAD];
    __shared__ float bS[2][128][PAD];
    __shared__ int rowIdx[128];

    const int tid  = threadIdx.x;
    const int lane = tid & 31;
    const int wid  = tid >> 5;
    const int wm   = wid & 1;
    const int wn   = wid >> 1;
    const int g    = lane >> 2;
    const int t    = lane & 3;
    const int l7   = lane & 7;
    const int lb8  = (lane >> 3) & 1;
    const int lh4  = lane >> 4;

    const int n0    = blockIdx.x * 128;
    const int mtile = blockIdx.y;

    int split = *split_ptr;
    if (split < 0) split = 0;
    if (split > SEQ) split = SEQ;
    const int textRows = BATCH * split;

    if (tid < 128) {
        int idx = mtile * 128 + tid;
        int r;
        if (idx < textRows) {
            int b = (split > 0) ? (idx / split) : 0;
            int tt = (split > 0) ? (idx - b * split) : 0;
            r = b * SEQ + tt;
        } else {
            int per = SEQ - split;
            int j = idx - textRows;
            int b = (per > 0) ? (j / per) : 0;
            int tt = split + ((per > 0) ? (j - b * per) : 0);
            r = b * SEQ + tt;
        }
        rowIdx[tid] = r;
    }
    const bool isText = (mtile * 128) < textRows;
    const float* __restrict__ W    = isText ? Wt : Wi;
    const float* __restrict__ bias = isText ? bt : bi;
    __syncthreads();

    const int m_of[2]  = { (tid + 0) >> 2, (tid + 256) >> 2 };
    const int c4       = tid & 3;

    const uint32_t aAddr[2] = {
        smem_u32(&aS[0][wm * 64 + l7 + lb8 * 8][lh4 * 4]),
        smem_u32(&aS[1][wm * 64 + l7 + lb8 * 8][lh4 * 4])
    };
    const uint32_t bAddr[2] = {
        smem_u32(&bS[0][wn * 32 + lh4 * 8 + l7][lb8 * 4]),
        smem_u32(&bS[1][wn * 32 + lh4 * 8 + l7][lb8 * 4])
    };

    float acc[4][4][4];
#pragma unroll
    for (int mt = 0; mt < 4; mt++)
#pragma unroll
        for (int nt = 0; nt < 4; nt++)
#pragma unroll
            for (int c = 0; c < 4; c++) acc[mt][nt][c] = 0.f;

#pragma unroll
    for (int i = 0; i < 2; i++) {
        int m = m_of[i];
        float4 va = *(const float4*)(X + (size_t)rowIdx[m] * EMB + c4 * 4);
        float4 vb = *(const float4*)(W + (size_t)(n0 + m) * EMB + c4 * 4);
        va.x = to_tf32(va.x); va.y = to_tf32(va.y);
        va.z = to_tf32(va.z); va.w = to_tf32(va.w);
        vb.x = to_tf32(vb.x); vb.y = to_tf32(vb.y);
        vb.z = to_tf32(vb.z); vb.w = to_tf32(vb.w);
        *(float4*)&aS[0][m][c4 * 4] = va;
        *(float4*)&bS[0][m][c4 * 4] = vb;
    }
    __syncthreads();

    for (int ic = 0; ic < NCHK; ic++) {
        const int p = ic & 1;
        float4 pa[2], pb[2];
        const bool more = (ic + 1) < NCHK;
        if (more) {
            const int k0 = (ic + 1) * GKC;
#pragma unroll
            for (int i = 0; i < 2; i++) {
                int m = m_of[i];
                pa[i] = *(const float4*)(X + (size_t)rowIdx[m] * EMB + k0 + c4 * 4);
                pb[i] = *(const float4*)(W + (size_t)(n0 + m) * EMB + k0 + c4 * 4);
            }
        }

#pragma unroll
        for (int ks = 0; ks < 2; ks++) {
            uint32_t afr[4][4];
#pragma unroll
            for (int mt = 0; mt < 4; mt++)
                LDSM_X4(afr[mt][0], afr[mt][1], afr[mt][2], afr[mt][3],
                        aAddr[p] + (uint32_t)((mt * 16 * PAD + ks * 8) * 4));
            uint32_t bfr[4][2];
#pragma unroll
            for (int ntp = 0; ntp < 2; ntp++)
                LDSM_X4(bfr[2 * ntp][0], bfr[2 * ntp][1],
                        bfr[2 * ntp + 1][0], bfr[2 * ntp + 1][1],
                        bAddr[p] + (uint32_t)((ntp * 16 * PAD + ks * 8) * 4));
#pragma unroll
            for (int mt = 0; mt < 4; mt++)
#pragma unroll
                for (int nt = 0; nt < 4; nt++)
                    MMA_TF32(acc[mt][nt],
                             afr[mt][0], afr[mt][1], afr[mt][2], afr[mt][3],
                             bfr[nt][0], bfr[nt][1]);
        }

        if (more) {
#pragma unroll
            for (int i = 0; i < 2; i++) {
                int m = m_of[i];
                float4 va = pa[i], vb = pb[i];
                va.x = to_tf32(va.x); va.y = to_tf32(va.y);
                va.z = to_tf32(va.z); va.w = to_tf32(va.w);
                vb.x = to_tf32(vb.x); vb.y = to_tf32(vb.y);
                vb.z = to_tf32(vb.z); vb.w = to_tf32(vb.w);
                *(float4*)&aS[p ^ 1][m][c4 * 4] = va;
                *(float4*)&bS[p ^ 1][m][c4 * 4] = vb;
            }
        }
        __syncthreads();
    }

#pragma unroll
    for (int mt = 0; mt < 4; mt++) {
        const int r0 = rowIdx[wm * 64 + mt * 16 + g];
        const int r1 = rowIdx[wm * 64 + mt * 16 + g + 8];
#pragma unroll
        for (int nt = 0; nt < 4; nt++) {
            const int nc = n0 + wn * 32 + nt * 8 + t * 2;
            float2 bb = *(const float2*)(bias + nc);
            float2 o;
            o.x = (acc[mt][nt][0] + bb.x) * alpha;
            o.y = (acc[mt][nt][1] + bb.y) * alpha;
            *(float2*)(Y + (size_t)r0 * EMB + nc) = o;
            o.x = (acc[mt][nt][2] + bb.x) * alpha;
            o.y = (acc[mt][nt][3] + bb.y) * alpha;
            *(float2*)(Y + (size_t)r1 * EMB + nc) = o;
        }
    }
}

// =====================  mma.sync tf32 flash attention  =======================
// R9 config (best measured attn: 336us): Q fragments resident in registers,
// K/P via ldmatrix, V via scalar LDS, occ 1.
#define ATP 68

__global__ __launch_bounds__(256) void attn_mma(
    const float* __restrict__ Q, const float* __restrict__ K,
    const float* __restrict__ V, const float* __restrict__ mask,
    float* __restrict__ O)
{
    extern __shared__ float dynsm[];
    float (*pS)[ATP] = (float(*)[ATP])(dynsm);              // 128 x 68 (Q stage / P)
    float (*kS)[ATP] = (float(*)[ATP])(dynsm + 128 * ATP);  // 64 x 68
    float (*vS)[ATP] = (float(*)[ATP])(dynsm + 192 * ATP);  // 64 x 68
    float (*lred)[2] = (float(*)[2])(dynsm + 256 * ATP);    // 128 x 2

    const int tid  = threadIdx.x;
    const int lane = tid & 31;
    const int wid  = tid >> 5;
    const int wm   = wid >> 1;
    const int wn   = wid & 1;
    const int g    = lane >> 2;
    const int t    = lane & 3;
    const int l7   = lane & 7;
    const int lb8  = (lane >> 3) & 1;
    const int lh4  = lane >> 4;

    const int t0 = blockIdx.x * 128;
    const int h  = blockIdx.y;
    const int b  = blockIdx.z;

    const float* Qb = Q + ((size_t)b * SEQ + t0) * EMB + h * HDIM;
    const float* Kb = K + (size_t)b * SEQ * EMB + h * HDIM;
    const float* Vb = V + (size_t)b * SEQ * EMB + h * HDIM;

    const uint32_t pAaddr = smem_u32(&pS[wm * 32 + l7 + lb8 * 8][lh4 * 4]);
    const uint32_t kBaddr = smem_u32(&kS[wn * 32 + lh4 * 8 + l7][lb8 * 4]);

    // ---- stage Q tile -> pS, then pull A-fragments into registers ----
#pragma unroll
    for (int i = 0; i < 8; i++) {
        int id = tid + i * 256;
        int r = id >> 4, d4 = id & 15;
        float4 v = *(const float4*)(Qb + (size_t)r * EMB + d4 * 4);
        v.x = to_tf32(v.x); v.y = to_tf32(v.y);
        v.z = to_tf32(v.z); v.w = to_tf32(v.w);
        *(float4*)&pS[r][d4 * 4] = v;
    }
    __syncthreads();
    uint32_t qf[2][8][4];
#pragma unroll
    for (int mt = 0; mt < 2; mt++)
#pragma unroll
        for (int ks = 0; ks < 8; ks++)
            LDSM_X4(qf[mt][ks][0], qf[mt][ks][1], qf[mt][ks][2], qf[mt][ks][3],
                    pAaddr + (uint32_t)((mt * 16 * ATP + ks * 8) * 4));
    __syncthreads();

    // ---- stage K/V block 0 ----
#pragma unroll
    for (int i = 0; i < 4; i++) {
        int id = tid + i * 256;
        int s = id >> 4, d4 = id & 15;
        float4 kv = *(const float4*)(Kb + (size_t)s * EMB + d4 * 4);
        float4 vv = *(const float4*)(Vb + (size_t)s * EMB + d4 * 4);
        kv.x = to_tf32(kv.x); kv.y = to_tf32(kv.y);
        kv.z = to_tf32(kv.z); kv.w = to_tf32(kv.w);
        vv.x = to_tf32(vv.x); vv.y = to_tf32(vv.y);
        vv.z = to_tf32(vv.z); vv.w = to_tf32(vv.w);
        *(float4*)&kS[s][d4 * 4] = kv;
        *(float4*)&vS[s][d4 * 4] = vv;
    }
    __syncthreads();

    float oa[2][4][4];
#pragma unroll
    for (int mt = 0; mt < 2; mt++)
#pragma unroll
        for (int nt = 0; nt < 4; nt++)
#pragma unroll
            for (int c = 0; c < 4; c++) oa[mt][nt][c] = 0.f;
    float lp[2][2] = {{0.f, 0.f}, {0.f, 0.f}};

    for (int ic = 0; ic < SEQ / 64; ic++) {
        const int s0 = ic * 64;
        const bool more = (ic + 1) < SEQ / 64;
        float4 pk[4], pv[4];
        if (more) {
            const int sn = s0 + 64;
#pragma unroll
            for (int i = 0; i < 4; i++) {
                int id = tid + i * 256;
                int s = id >> 4, d4 = id & 15;
                pk[i] = *(const float4*)(Kb + (size_t)(sn + s) * EMB + d4 * 4);
                pv[i] = *(const float4*)(Vb + (size_t)(sn + s) * EMB + d4 * 4);
            }
        }

        // ---- S = Q K^T ----
        float sa[2][4][4];
#pragma unroll
        for (int mt = 0; mt < 2; mt++)
#pragma unroll
            for (int nt = 0; nt < 4; nt++)
#pragma unroll
                for (int c = 0; c < 4; c++) sa[mt][nt][c] = 0.f;
#pragma unroll
        for (int ks = 0; ks < 8; ks++) {
            uint32_t bk[4][2];
#pragma unroll
            for (int ntp = 0; ntp < 2; ntp++)
                LDSM_X4(bk[2 * ntp][0], bk[2 * ntp][1],
                        bk[2 * ntp + 1][0], bk[2 * ntp + 1][1],
                        kBaddr + (uint32_t)((ntp * 16 * ATP + ks * 8) * 4));
#pragma unroll
            for (int mt = 0; mt < 2; mt++)
#pragma unroll
                for (int nt = 0; nt < 4; nt++)
                    MMA_TF32(sa[mt][nt],
                             qf[mt][ks][0], qf[mt][ks][1],
                             qf[mt][ks][2], qf[mt][ks][3],
                             bk[nt][0], bk[nt][1]);
        }

        // ---- mask + exp, accumulate l, write P (tf32) to pS ----
#pragma unroll
        for (int mt = 0; mt < 2; mt++) {
            const int lr0 = wm * 32 + mt * 16 + g;
            const size_t gr0 = (size_t)(t0 + lr0) * SEQ + s0;
            const size_t gr1 = gr0 + (size_t)8 * SEQ;
#pragma unroll
            for (int nt = 0; nt < 4; nt++) {
                const int c = wn * 32 + nt * 8 + 2 * t;
                float2 m0 = *(const float2*)(mask + gr0 + c);
                float2 m1 = *(const float2*)(mask + gr1 + c);
                float p00 = __expf(sa[mt][nt][0] + m0.x);
                float p01 = __expf(sa[mt][nt][1] + m0.y);
                float p10 = __expf(sa[mt][nt][2] + m1.x);
                float p11 = __expf(sa[mt][nt][3] + m1.y);
                lp[mt][0] += p00 + p01;
                lp[mt][1] += p10 + p11;
                float2 st;
                st.x = to_tf32(p00); st.y = to_tf32(p01);
                *(float2*)&pS[lr0][c] = st;
                st.x = to_tf32(p10); st.y = to_tf32(p11);
                *(float2*)&pS[lr0 + 8][c] = st;
            }
        }
        __syncthreads();

        // ---- O += P V ----
#pragma unroll
        for (int ks = 0; ks < 8; ks++) {
            const int kc = ks * 8 + t;
            uint32_t af[2][4];
#pragma unroll
            for (int mt = 0; mt < 2; mt++)
                LDSM_X4(af[mt][0], af[mt][1], af[mt][2], af[mt][3],
                        pAaddr + (uint32_t)((mt * 16 * ATP + ks * 8) * 4));
            uint32_t bv[4][2];
#pragma unroll
            for (int nt = 0; nt < 4; nt++) {
                const int cn = wn * 32 + nt * 8 + g;
                bv[nt][0] = __float_as_uint(vS[kc][cn]);
                bv[nt][1] = __float_as_uint(vS[kc + 4][cn]);
            }
#pragma unroll
            for (int mt = 0; mt < 2; mt++)
#pragma unroll
                for (int nt = 0; nt < 4; nt++)
                    MMA_TF32(oa[mt][nt],
                             af[mt][0], af[mt][1], af[mt][2], af[mt][3],
                             bv[nt][0], bv[nt][1]);
        }
        __syncthreads();

        if (more) {
#pragma unroll
            for (int i = 0; i < 4; i++) {
                int id = tid + i * 256;
                int s = id >> 4, d4 = id & 15;
                float4 kv = pk[i], vv = pv[i];
                kv.x = to_tf32(kv.x); kv.y = to_tf32(kv.y);
                kv.z = to_tf32(kv.z); kv.w = to_tf32(kv.w);
                vv.x = to_tf32(vv.x); vv.y = to_tf32(vv.y);
                vv.z = to_tf32(vv.z); vv.w = to_tf32(vv.w);
                *(float4*)&kS[s][d4 * 4] = kv;
                *(float4*)&vS[s][d4 * 4] = vv;
            }
            __syncthreads();
        }
    }

    // ---- row-sum reduction ----
#pragma unroll
    for (int mt = 0; mt < 2; mt++) {
#pragma unroll
        for (int j = 0; j < 2; j++) {
            lp[mt][j] += __shfl_xor_sync(0xffffffffu, lp[mt][j], 1);
            lp[mt][j] += __shfl_xor_sync(0xffffffffu, lp[mt][j], 2);
        }
    }
    if (t == 0) {
#pragma unroll
        for (int mt = 0; mt < 2; mt++) {
            lred[wm * 32 + mt * 16 + g][wn]     = lp[mt][0];
            lred[wm * 32 + mt * 16 + g + 8][wn] = lp[mt][1];
        }
    }
    __syncthreads();

    float* Ob = O + ((size_t)b * SEQ + t0) * EMB + h * HDIM;
#pragma unroll
    for (int mt = 0; mt < 2; mt++) {
        const int lr0 = wm * 32 + mt * 16 + g;
        const float inv0 = 1.f / (lred[lr0][0] + lred[lr0][1]);
        const float inv1 = 1.f / (lred[lr0 + 8][0] + lred[lr0 + 8][1]);
#pragma unroll
        for (int nt = 0; nt < 4; nt++) {
            const int c = wn * 32 + nt * 8 + 2 * t;
            float2 o;
            o.x = oa[mt][nt][0] * inv0;
            o.y = oa[mt][nt][1] * inv0;
            *(float2*)(Ob + (size_t)lr0 * EMB + c) = o;
            o.x = oa[mt][nt][2] * inv1;
            o.y = oa[mt][nt][3] * inv1;
            *(float2*)(Ob + (size_t)(lr0 + 8) * EMB + c) = o;
        }
    }
}

#define ATTN_SMEM ((256 * ATP + 256) * 4)

// ---------------- multiway layernorm over last dim (E=1024) -----------------
__global__ __launch_bounds__(256) void ln_kernel(
    const float* __restrict__ A, float* __restrict__ Xo,
    const float* __restrict__ gt, const float* __restrict__ bt,
    const float* __restrict__ gi, const float* __restrict__ bi,
    const int* __restrict__ split_ptr)
{
    const int r = blockIdx.x;
    const int t = r & (SEQ - 1);
    const int split = *split_ptr;
    const float* g  = (t < split) ? gt : gi;
    const float* bb = (t < split) ? bt : bi;

    const int tid = threadIdx.x;
    float4 v = ((const float4*)(A + (size_t)r * EMB))[tid];

    float s  = v.x + v.y + v.z + v.w;
    float sq = v.x * v.x + v.y * v.y + v.z * v.z + v.w * v.w;

    __shared__ float ssum[8], ssq[8];
#pragma unroll
    for (int off = 16; off > 0; off >>= 1) {
        s  += __shfl_down_sync(0xffffffffu, s, off);
        sq += __shfl_down_sync(0xffffffffu, sq, off);
    }
    if ((tid & 31) == 0) { ssum[tid >> 5] = s; ssq[tid >> 5] = sq; }
    __syncthreads();

    __shared__ float mu_s, rs_s;
    if (tid == 0) {
        float S = 0.f, Qq = 0.f;
#pragma unroll
        for (int i = 0; i < 8; i++) { S += ssum[i]; Qq += ssq[i]; }
        float mu  = S * (1.f / EMB);
        float var = Qq * (1.f / EMB) - mu * mu;
        mu_s = mu;
        rs_s = rsqrtf(var + 1e-5f);
    }
    __syncthreads();
    float mu = mu_s, rstd = rs_s;

    float4 g4 = ((const float4*)g)[tid];
    float4 b4 = ((const float4*)bb)[tid];
    float4 y;
    y.x = (v.x - mu) * rstd * g4.x + b4.x;
    y.y = (v.y - mu) * rstd * g4.y + b4.y;
    y.z = (v.z - mu) * rstd * g4.z + b4.z;
    y.w = (v.w - mu) * rstd * g4.w + b4.w;
    ((float4*)(Xo + (size_t)r * EMB))[tid] = y;
}

// ---------------- launch ------------------------------------------------------
extern "C" void kernel_launch(void* const* d_in, const int* in_sizes, int n_in,
                              void* d_out, int out_size)
{
    const float* query = (const float*)d_in[0];
    const float* key   = (const float*)d_in[1];
    const float* value = (const float*)d_in[2];
    const float* mask  = (const float*)d_in[3];
    const float* Wq_t = (const float*)d_in[4];  const float* bq_t = (const float*)d_in[5];
    const float* Wq_i = (const float*)d_in[6];  const float* bq_i = (const float*)d_in[7];
    const float* Wk_t = (const float*)d_in[8];  const float* bk_t = (const float*)d_in[9];
    const float* Wk_i = (const float*)d_in[10]; const float* bk_i = (const float*)d_in[11];
    const float* Wv_t = (const float*)d_in[12]; const float* bv_t = (const float*)d_in[13];
    const float* Wv_i = (const float*)d_in[14]; const float* bv_i = (const float*)d_in[15];
    const float* Wo_t = (const float*)d_in[16]; const float* bo_t = (const float*)d_in[17];
    const float* Wo_i = (const float*)d_in[18]; const float* bo_i = (const float*)d_in[19];
    const float* lng_t = (const float*)d_in[20]; const float* lnb_t = (const float*)d_in[21];
    const float* lng_i = (const float*)d_in[22]; const float* lnb_i = (const float*)d_in[23];
    const int*   split = (const int*)d_in[24];

    float *Q, *K, *V, *A, *X;
    cudaGetSymbolAddress((void**)&Q, g_Q);
    cudaGetSymbolAddress((void**)&K, g_K);
    cudaGetSymbolAddress((void**)&V, g_V);
    cudaGetSymbolAddress((void**)&A, g_A);
    cudaGetSymbolAddress((void**)&X, g_X);

    const float scaling = 0.125f; // HD^-0.5, HD=64

    // one-time setup (runs on the correctness call, NOT during capture):
    // func attrs + side streams/events for the QKV fork-join.
    static cudaStream_t s1 = nullptr, s2 = nullptr;
    static cudaEvent_t evFork = nullptr, evK = nullptr, evV = nullptr;
    static bool init_done = false;
    if (!init_done) {
        cudaFuncSetAttribute(attn_mma, cudaFuncAttributeMaxDynamicSharedMemorySize,
                             ATTN_SMEM);
        cudaStreamCreateWithFlags(&s1, cudaStreamNonBlocking);
        cudaStreamCreateWithFlags(&s2, cudaStreamNonBlocking);
        cudaEventCreateWithFlags(&evFork, cudaEventDisableTiming);
        cudaEventCreateWithFlags(&evK, cudaEventDisableTiming);
        cudaEventCreateWithFlags(&evV, cudaEventDisableTiming);
        init_done = true;
    }

    dim3 gg(EMB / 128, (BATCH * SEQ) / 128);

    // fork: K and V projections run on side streams, overlapped with Q.
    cudaEventRecord(evFork, 0);
    cudaStreamWaitEvent(s1, evFork, 0);
    cudaStreamWaitEvent(s2, evFork, 0);

    mw_gemm_mma<<<gg, 256>>>(query, Wq_t, bq_t, Wq_i, bq_i, Q, split, scaling);
    mw_gemm_mma<<<gg, 256, 0, s1>>>(key,   Wk_t, bk_t, Wk_i, bk_i, K, split, 1.f);
    mw_gemm_mma<<<gg, 256, 0, s2>>>(value, Wv_t, bv_t, Wv_i, bv_i, V, split, 1.f);

    // join: attention needs Q, K and V.
    cudaEventRecord(evK, s1);
    cudaEventRecord(evV, s2);
    cudaStreamWaitEvent(0, evK, 0);
    cudaStreamWaitEvent(0, evV, 0);

    dim3 ga(SEQ / 128, NHEAD, BATCH);
    attn_mma<<<ga, 256, ATTN_SMEM>>>(Q, K, V, mask, A);

    ln_kernel<<<BATCH * SEQ, 256>>>(A, X, lng_t, lnb_t, lng_i, lnb_i, split);

    mw_gemm_mma<<<gg, 256>>>(X, Wo_t, bo_t, Wo_i, bo_i, (float*)d_out, split, 1.f);
}